// round 1
// baseline (speedup 1.0000x reference)
#include <cuda_runtime.h>
#include <math.h>

// Problem dims (hardcoded per reference: B=2, C=2, D=64, H=128, W=128)
#define DD 64
#define HH 128
#define WW 128
#define VOLSZ (DD*HH*WW)       // 1,048,576 = 2^20
#define NTOT  (2*VOLSZ)        // 2,097,152 = 2^21
#define HWS   (HH*WW)          // 16384 = 2^14
#define NV4   (NTOT/4)
#define GV    (NV4/256)        // 2048 blocks (vector kernels)
#define GS    (NTOT/256)       // 8192 blocks (scalar kernels)

// ---------------- scratch (device globals; no cudaMalloc allowed) ----------
__device__ float g_P[NTOT];    // prob
__device__ float g_Y[NTOT];    // y_true (0/1)
__device__ float g_Hd[NTOT];   // hard = prob > 0.5
__device__ float g_ST[NTOT];   // skel_true = soft_skel(Y)
__device__ float g_SP[NTOT];   // skel_pred = soft_skel(P)
__device__ float g_SPH[NTOT];  // skel_pred_hard = soft_skel(H)
__device__ float g_accT[NTOT]; // edt accumulator (Y)
__device__ float g_accP[NTOT]; // edt accumulator (H)
__device__ float g_A[NTOT];
__device__ float g_Bb[NTOT];
__device__ float g_E[NTOT];

__device__ double g_sums[14];
__device__ int g_maxT[2], g_minT[2], g_maxP[2], g_minP[2];

enum { S_TP=0, S_FP, S_FN, S_CE, S_CONN, S_DIR,
       S_CL1, S_CL2, S_CL3, S_CL4, S_I1, S_U1, S_I2, S_U2 };

// ---------------- small helpers ----------------
__device__ __forceinline__ float4 ld4(const float* p){ return *reinterpret_cast<const float4*>(p); }
__device__ __forceinline__ void   st4(float* p, float4 v){ *reinterpret_cast<float4*>(p) = v; }

__device__ __forceinline__ float4 f4min(float4 a, float4 b){
  return make_float4(fminf(a.x,b.x), fminf(a.y,b.y), fminf(a.z,b.z), fminf(a.w,b.w));
}
__device__ __forceinline__ float4 f4max(float4 a, float4 b){
  return make_float4(fmaxf(a.x,b.x), fmaxf(a.y,b.y), fmaxf(a.z,b.z), fmaxf(a.w,b.w));
}

template<bool MX> __device__ __forceinline__ float opf(float a, float b){
  return MX ? fmaxf(a,b) : fminf(a,b);
}
template<bool MX> __device__ __forceinline__ float4 opf4(float4 a, float4 b){
  return MX ? f4max(a,b) : f4min(a,b);
}

// 3-wide sliding window (dx in {-1,0,1}) over 4 consecutive w-outputs.
template<bool MX>
__device__ __forceinline__ float4 rowwin3(const float* rp, int w0){
  const float pad = MX ? -1e30f : 1e30f;
  float  l  = (w0 > 0)      ? rp[-1] : pad;
  float4 v  = ld4(rp);
  float  rr = (w0 + 4 < WW) ? rp[4]  : pad;
  float4 o;
  o.x = opf<MX>(opf<MX>(l,  v.x), v.y);
  o.y = opf<MX>(opf<MX>(v.x,v.y), v.z);
  o.z = opf<MX>(opf<MX>(v.y,v.z), v.w);
  o.w = opf<MX>(opf<MX>(v.z,v.w), rr);
  return o;
}

// 3x3x3 box pool (SAME padding = ignore OOB), vectorized over 4 w-outputs.
template<bool MX>
__device__ __forceinline__ float4 box27(const float* cp, int d, int hh, int w0){
  const float pad = MX ? -1e30f : 1e30f;
  float4 m = make_float4(pad, pad, pad, pad);
  #pragma unroll
  for (int dz=-1; dz<=1; ++dz){
    if ((unsigned)(d+dz) >= DD) continue;
    #pragma unroll
    for (int dy=-1; dy<=1; ++dy){
      if ((unsigned)(hh+dy) >= HH) continue;
      m = opf4<MX>(m, rowwin3<MX>(cp + dz*HWS + dy*WW, w0));
    }
  }
  return m;
}

// ---------------- block reductions ----------------
__device__ __forceinline__ float warp_sum(float v){
  #pragma unroll
  for (int o=16; o; o>>=1) v += __shfl_down_sync(0xffffffffu, v, o);
  return v;
}
__device__ __forceinline__ void block_add(double* dst, float v){
  __shared__ float sh[8];
  v = warp_sum(v);
  if ((threadIdx.x & 31) == 0) sh[threadIdx.x >> 5] = v;
  __syncthreads();
  if (threadIdx.x == 0){
    float t = sh[0]+sh[1]+sh[2]+sh[3]+sh[4]+sh[5]+sh[6]+sh[7];
    atomicAdd(dst, (double)t);
  }
  __syncthreads();
}
__device__ __forceinline__ void block_maxf(int* dst, float v){
  __shared__ float sh[8];
  #pragma unroll
  for (int o=16; o; o>>=1) v = fmaxf(v, __shfl_down_sync(0xffffffffu, v, o));
  if ((threadIdx.x & 31) == 0) sh[threadIdx.x >> 5] = v;
  __syncthreads();
  if (threadIdx.x == 0){
    float m = sh[0];
    #pragma unroll
    for (int k=1;k<8;k++) m = fmaxf(m, sh[k]);
    atomicMax(dst, __float_as_int(m));   // values >= 0 -> int compare valid
  }
  __syncthreads();
}
__device__ __forceinline__ void block_minf(int* dst, float v){
  __shared__ float sh[8];
  #pragma unroll
  for (int o=16; o; o>>=1) v = fminf(v, __shfl_down_sync(0xffffffffu, v, o));
  if ((threadIdx.x & 31) == 0) sh[threadIdx.x >> 5] = v;
  __syncthreads();
  if (threadIdx.x == 0){
    float m = sh[0];
    #pragma unroll
    for (int k=1;k<8;k++) m = fminf(m, sh[k]);
    atomicMin(dst, __float_as_int(m));
  }
  __syncthreads();
}

// ---------------- kernels ----------------
__global__ void zero_kernel(){
  int t = threadIdx.x;
  if (t < 14) g_sums[t] = 0.0;
  if (t < 2){
    g_maxT[t] = 0; g_maxP[t] = 0;
    g_minT[t] = 0x7f800000; g_minP[t] = 0x7f800000;  // +inf
  }
}

// prob/y/hard + dice sums + CE + connectivity
__global__ void __launch_bounds__(256) init_kernel(const float* __restrict__ net,
                                                   const int* __restrict__ tgt){
  int t = blockIdx.x*256 + threadIdx.x;
  int i = t << 2;
  int b = i >> 20;
  float4 n0 = ld4(net + i + b*VOLSZ);
  float4 n1 = ld4(net + i + (b+1)*VOLSZ);
  int4   tg = *reinterpret_cast<const int4*>(tgt + i);
  float a[4] = {n0.x, n0.y, n0.z, n0.w};
  float c[4] = {n1.x, n1.y, n1.z, n1.w};
  int   l[4] = {tg.x, tg.y, tg.z, tg.w};
  float pv[4], yv[4], hv[4];
  float tp=0.f, fp=0.f, fn=0.f, ce=0.f, cn=0.f;
  #pragma unroll
  for (int k=0;k<4;k++){
    float y = (l[k] > 0) ? 1.f : 0.f;
    float p = 1.f / (1.f + expf(a[k] - c[k]));      // softmax([n0,n1])[1]
    pv[k]=p; yv[k]=y; hv[k] = (p > 0.5f) ? 1.f : 0.f;
    tp += p*y; fp += p*(1.f-y); fn += (1.f-p)*y;
    float m = fmaxf(a[k], c[k]);
    float lse = m + logf(expf(a[k]-m) + expf(c[k]-m));
    ce += lse - ((l[k] > 0) ? c[k] : a[k]);
    cn += fabsf(((a[k] > 0.5f) ? 1.f : 0.f) - y)
        + fabsf(((c[k] > 0.5f) ? 1.f : 0.f) - y);
  }
  st4(g_P  + i, make_float4(pv[0],pv[1],pv[2],pv[3]));
  st4(g_Y  + i, make_float4(yv[0],yv[1],yv[2],yv[3]));
  st4(g_Hd + i, make_float4(hv[0],hv[1],hv[2],hv[3]));
  block_add(&g_sums[S_TP], tp);
  block_add(&g_sums[S_FP], fp);
  block_add(&g_sums[S_FN], fn);
  block_add(&g_sums[S_CE], ce);
  block_add(&g_sums[S_CONN], cn);
}

// directional (Sobel) loss — replicates the reference's exact kernel layout:
// gx: deriv w, smooth(1,2,1) in h; gy: deriv w, smooth in d; gz: deriv d, smooth in w.
__global__ void __launch_bounds__(256) dir_kernel(const float* __restrict__ net,
                                                  const int* __restrict__ tgt){
  int t = blockIdx.x*256 + threadIdx.x;
  int i = t << 2;
  int b = i >> 20;
  int r = i & (VOLSZ-1);
  int d = r >> 14, hh = (r >> 7) & 127, w0 = r & 127;
  const float* pb = net + i + b*VOLSZ;   // channel 0
  const int*   tb = tgt + i;
  float pgx[4]={0,0,0,0}, pgy[4]={0,0,0,0}, pgz[4]={0,0,0,0};
  float tgx[4]={0,0,0,0}, tgy[4]={0,0,0,0}, tgz[4]={0,0,0,0};
  #pragma unroll
  for (int dz=-1; dz<=1; ++dz){
    if ((unsigned)(d+dz) >= DD) continue;
    float cy = (dz==0) ? 2.f : 1.f;
    float cz = (float)dz;
    #pragma unroll
    for (int dy=-1; dy<=1; ++dy){
      if ((unsigned)(hh+dy) >= HH) continue;
      float cx = (dy==0) ? 2.f : 1.f;
      int off = dz*HWS + dy*WW;
      { // pred field (zero-padded along w)
        const float* rp = pb + off;
        float vv[6];
        vv[0] = (w0 > 0) ? rp[-1] : 0.f;
        float4 v = ld4(rp);
        vv[1]=v.x; vv[2]=v.y; vv[3]=v.z; vv[4]=v.w;
        vv[5] = (w0 + 4 < WW) ? rp[4] : 0.f;
        #pragma unroll
        for (int k=0;k<4;k++){
          float dv = vv[k+2] - vv[k];
          float sv = vv[k] + 2.f*vv[k+1] + vv[k+2];
          pgx[k] += cx*dv; pgy[k] += cy*dv; pgz[k] += cz*sv;
        }
      }
      { // target field
        const int* rp = tb + off;
        float vv[6];
        vv[0] = (w0 > 0) ? (float)rp[-1] : 0.f;
        int4 v = *reinterpret_cast<const int4*>(rp);
        vv[1]=(float)v.x; vv[2]=(float)v.y; vv[3]=(float)v.z; vv[4]=(float)v.w;
        vv[5] = (w0 + 4 < WW) ? (float)rp[4] : 0.f;
        #pragma unroll
        for (int k=0;k<4;k++){
          float dv = vv[k+2] - vv[k];
          float sv = vv[k] + 2.f*vv[k+1] + vv[k+2];
          tgx[k] += cx*dv; tgy[k] += cy*dv; tgz[k] += cz*sv;
        }
      }
    }
  }
  float acc = 0.f;
  #pragma unroll
  for (int k=0;k<4;k++){
    float np = sqrtf(pgx[k]*pgx[k] + pgy[k]*pgy[k] + pgz[k]*pgz[k]);
    float nt = sqrtf(tgx[k]*tgx[k] + tgy[k]*tgy[k] + tgz[k]*tgz[k]);
    float ip = 1.f / fmaxf(np, 1e-12f);
    float it = 1.f / fmaxf(nt, 1e-12f);
    float num = (pgx[k]*tgx[k] + pgy[k]*tgy[k] + pgz[k]*tgz[k]) * ip * it;
    float den = fmaxf((np*ip) * (nt*it), 1e-8f);
    acc += num / den;
  }
  block_add(&g_sums[S_DIR], acc);
}

// soft_erode: min over 7-point cross
__global__ void __launch_bounds__(256) erode_kernel(const float* __restrict__ src,
                                                    float* __restrict__ dst){
  int t = blockIdx.x*256 + threadIdx.x;
  int i = t << 2;
  int r = i & (VOLSZ-1);
  int d = r >> 14, hh = (r >> 7) & 127, w0 = r & 127;
  float4 m = rowwin3<false>(src + i, w0);
  if (hh > 0)     m = f4min(m, ld4(src + i - WW));
  if (hh < HH-1)  m = f4min(m, ld4(src + i + WW));
  if (d > 0)      m = f4min(m, ld4(src + i - HWS));
  if (d < DD-1)   m = f4min(m, ld4(src + i + HWS));
  st4(dst + i, m);
}

// skel = relu(img - dilate27(eroded))
__global__ void __launch_bounds__(256) dilate_init_kernel(const float* __restrict__ img,
                                                          const float* __restrict__ er,
                                                          float* __restrict__ skel){
  int t = blockIdx.x*256 + threadIdx.x;
  int i = t << 2;
  int r = i & (VOLSZ-1);
  int d = r >> 14, hh = (r >> 7) & 127, w0 = r & 127;
  float4 o  = box27<true>(er + i, d, hh, w0);
  float4 im = ld4(img + i);
  st4(skel + i, make_float4(fmaxf(im.x-o.x,0.f), fmaxf(im.y-o.y,0.f),
                            fmaxf(im.z-o.z,0.f), fmaxf(im.w-o.w,0.f)));
}

// delta = relu(img - dilate27(er)); skel += relu(delta - skel*delta)
__global__ void __launch_bounds__(256) dilate_update_kernel(const float* __restrict__ img,
                                                            const float* __restrict__ er,
                                                            float* __restrict__ skel){
  int t = blockIdx.x*256 + threadIdx.x;
  int i = t << 2;
  int r = i & (VOLSZ-1);
  int d = r >> 14, hh = (r >> 7) & 127, w0 = r & 127;
  float4 o  = box27<true>(er + i, d, hh, w0);
  float4 im = ld4(img + i);
  float4 s  = ld4(skel + i);
  float dl;
  dl = fmaxf(im.x-o.x,0.f); s.x += fmaxf(dl - s.x*dl, 0.f);
  dl = fmaxf(im.y-o.y,0.f); s.y += fmaxf(dl - s.y*dl, 0.f);
  dl = fmaxf(im.z-o.z,0.f); s.z += fmaxf(dl - s.z*dl, 0.f);
  dl = fmaxf(im.w-o.w,0.f); s.w += fmaxf(dl - s.w*dl, 0.f);
  st4(skel + i, s);
}

// edt step: acc (+)= cur ; nxt = minpool27(cur)
__global__ void __launch_bounds__(256) minpool_acc_kernel(const float* __restrict__ cur,
                                                          float* __restrict__ nxt,
                                                          float* __restrict__ acc,
                                                          int first){
  int t = blockIdx.x*256 + threadIdx.x;
  int i = t << 2;
  int r = i & (VOLSZ-1);
  int d = r >> 14, hh = (r >> 7) & 127, w0 = r & 127;
  float4 c = ld4(cur + i);
  float4 m = box27<false>(cur + i, d, hh, w0);
  st4(nxt + i, m);
  if (first){
    st4(acc + i, c);
  } else {
    float4 a = ld4(acc + i);
    a.x += c.x; a.y += c.y; a.z += c.z; a.w += c.w;
    st4(acc + i, a);
  }
}

// per-batch max/min of skel_radius for both get_weights calls
__global__ void __launch_bounds__(256) r1_kernel(){
  int i = blockIdx.x*256 + threadIdx.x;
  int b = i >> 20;                       // block never straddles batches
  float y = g_Y[i], st = g_ST[i], hd = g_Hd[i], sph = g_SPH[i], p = g_P[i];
  float srT = g_accT[i] * y * st;
  float sb  = (sph * p > 0.5f) ? 1.f : 0.f;
  float srP = g_accP[i] * hd * sb;
  block_maxf(&g_maxT[b], srT);
  block_minf(&g_minT[b], srT);
  block_maxf(&g_maxP[b], srP);
  block_minf(&g_minP[b], srP);
}

// all union-loss + clDice sums in one pass
__global__ void __launch_bounds__(256) r2_kernel(){
  int i = blockIdx.x*256 + threadIdx.x;
  int b = i >> 20;
  float y = g_Y[i], p = g_P[i], hd = g_Hd[i];
  float st = g_ST[i], sp = g_SP[i], sph = g_SPH[i];
  float rmaxT = fmaxf(__int_as_float(g_maxT[b]), 1.f);
  float rminT = fmaxf(__int_as_float(g_minT[b]), 1.f);
  float rmaxP = fmaxf(__int_as_float(g_maxP[b]), 1.f);
  float rminP = fmaxf(__int_as_float(g_minP[b]), 1.f);

  float dT  = g_accT[i] * y;
  float srT = dT * st;
  float q_vl = fminf(dT, rmaxT) / rmaxT * y;
  float t1 = (rmaxT - srT + rminT) / rmaxT;
  float q_sl = t1*t1 * st * st;

  float dP  = g_accP[i] * hd;
  float sb  = (sph * p > 0.5f) ? 1.f : 0.f;
  float srP = dP * sb;
  float q_vp = fminf(dP, rmaxP) / rmaxP * p;
  float t2 = (rmaxP - srP + rminP) / rmaxP;
  float q_sp = t2*t2 * sb * (sph * p);

  float i1 = q_sp * powf(q_sp + 1e-4f, 0.7f) * q_vl;
  float u1 = q_sp * (0.1f*q_sp + 0.9f*q_vl);
  float i2 = q_sl * powf(q_vp + 1e-4f, 0.7f) * q_sl;
  float u2 = q_sl * (0.1f*q_vp + 0.9f*q_sl);

  block_add(&g_sums[S_I1], i1);
  block_add(&g_sums[S_U1], u1);
  block_add(&g_sums[S_I2], i2);
  block_add(&g_sums[S_U2], u2);
  block_add(&g_sums[S_CL1], sp*y);
  block_add(&g_sums[S_CL2], sp);
  block_add(&g_sums[S_CL3], st*p);
  block_add(&g_sums[S_CL4], st);
}

__global__ void final_kernel(float* __restrict__ out){
  double tp = g_sums[S_TP], fp = g_sums[S_FP], fn = g_sums[S_FN];
  double dice = -((2.0*tp + 1e-5) / (2.0*tp + fp + fn + 1e-5));
  double ce   = g_sums[S_CE] / (double)NTOT;
  double conn = g_sums[S_CONN] / (2.0 * (double)NTOT);
  double dir  = 1.0 - g_sums[S_DIR] / (double)NTOT;
  double tprec = (g_sums[S_CL1] + 1.0) / (g_sums[S_CL2] + 1.0);
  double tsens = (g_sums[S_CL3] + 1.0) / (g_sums[S_CL4] + 1.0);
  double cl = 1.0 - 2.0*tprec*tsens / (tprec + tsens);
  double u  = (1.0 - (g_sums[S_I1] + 1.0) / (g_sums[S_U1] + 1.0))
            + (1.0 - (g_sums[S_I2] + 1.0) / (g_sums[S_U2] + 1.0));
  out[0] = (float)(dice + ce + cl + dir + conn + u);
}

// ---------------- host-side orchestration ----------------
static void run_skel(const float* src, float* skel, float* A, float* Bb, float* E){
  erode_kernel<<<GV,256>>>(src, E);
  dilate_init_kernel<<<GV,256>>>(src, E, skel);
  const float* cur = src;
  for (int it=0; it<10; ++it){
    float* nxt = (it & 1) ? Bb : A;
    erode_kernel<<<GV,256>>>(cur, nxt);
    erode_kernel<<<GV,256>>>(nxt, E);
    dilate_update_kernel<<<GV,256>>>(nxt, E, skel);
    cur = nxt;
  }
}

static void run_edt(const float* src, float* acc, float* A, float* Bb){
  const float* cur = src;
  for (int k=0; k<16; ++k){
    float* nxt = (k & 1) ? Bb : A;
    minpool_acc_kernel<<<GV,256>>>(cur, nxt, acc, (k==0) ? 1 : 0);
    cur = nxt;
  }
}

extern "C" void kernel_launch(void* const* d_in, const int* in_sizes, int n_in,
                              void* d_out, int out_size){
  (void)in_sizes; (void)n_in; (void)out_size;
  const float* net = (const float*)d_in[0];
  const int*   tgt = (const int*)d_in[1];
  float* out = (float*)d_out;

  float *P,*Y,*Hd,*ST,*SP,*SPH,*aT,*aP,*A,*Bb,*E;
  cudaGetSymbolAddress((void**)&P,   g_P);
  cudaGetSymbolAddress((void**)&Y,   g_Y);
  cudaGetSymbolAddress((void**)&Hd,  g_Hd);
  cudaGetSymbolAddress((void**)&ST,  g_ST);
  cudaGetSymbolAddress((void**)&SP,  g_SP);
  cudaGetSymbolAddress((void**)&SPH, g_SPH);
  cudaGetSymbolAddress((void**)&aT,  g_accT);
  cudaGetSymbolAddress((void**)&aP,  g_accP);
  cudaGetSymbolAddress((void**)&A,   g_A);
  cudaGetSymbolAddress((void**)&Bb,  g_Bb);
  cudaGetSymbolAddress((void**)&E,   g_E);

  zero_kernel<<<1,32>>>();
  init_kernel<<<GV,256>>>(net, tgt);
  dir_kernel<<<GV,256>>>(net, tgt);

  run_skel(Y,  ST,  A, Bb, E);   // skel_true (shared by clDice and union)
  run_skel(P,  SP,  A, Bb, E);   // skel_pred (prob) for clDice
  run_skel(Hd, SPH, A, Bb, E);   // skel_pred_hard for union

  run_edt(Y,  aT, A, Bb);        // edt_approx(y_true)
  run_edt(Hd, aP, A, Bb);        // edt_approx(hard)

  r1_kernel<<<GS,256>>>();
  r2_kernel<<<GS,256>>>();
  final_kernel<<<1,1>>>(out);
}

// round 2
// speedup vs baseline: 1.4242x; 1.4242x over previous
#include <cuda_runtime.h>
#include <math.h>

// Dims per reference: B=2, C=2, D=64, H=128, W=128
#define DD 64
#define HH 128
#define WW 128
#define VOLSZ (DD*HH*WW)       // 2^20
#define NTOT  (2*VOLSZ)        // 2^21 (one "field" = batch of 2 volumes)
#define HWS   (HH*WW)          // 2^14
#define GS    (NTOT/256)       // scalar-grid for reductions

// Tiled kernels: each thread = 4(w) x 4(h) outputs. Threads per field-item:
// 32(w-groups) * 32(h-groups) * 64(d) = 65536 = 2^16.
#define G_SKEL ((3*NTOT/16)/256)   // 1536 blocks (3 fields batched)
#define G_EDT  ((2*NTOT/16)/256)   // 1024 blocks (2 fields batched)
#define G_INIT ((NTOT/4)/256)      // 2048 blocks

// ---------------- scratch ----------------
// SRC: [Y | P | Hd], SK: [ST | SP | SPH]  (each field NTOT floats)
__device__ float g_SRC[3*NTOT];
__device__ float g_SK [3*NTOT];
__device__ float g_A  [3*NTOT];
__device__ float g_Bb [3*NTOT];
__device__ float g_E  [3*NTOT];
__device__ float g_ACC[2*NTOT];   // [edt(Y) | edt(Hd)]

__device__ double g_sums[14];
__device__ int g_maxT[2], g_minT[2], g_maxP[2], g_minP[2];

enum { S_TP=0, S_FP, S_FN, S_CE, S_CONN, S_DIR,
       S_CL1, S_CL2, S_CL3, S_CL4, S_I1, S_U1, S_I2, S_U2 };

// ---------------- helpers ----------------
__device__ __forceinline__ float4 ld4(const float* p){ return *reinterpret_cast<const float4*>(p); }
__device__ __forceinline__ void   st4(float* p, float4 v){ *reinterpret_cast<float4*>(p) = v; }
__device__ __forceinline__ float4 f4min(float4 a, float4 b){
  return make_float4(fminf(a.x,b.x), fminf(a.y,b.y), fminf(a.z,b.z), fminf(a.w,b.w));
}
__device__ __forceinline__ float4 f4max(float4 a, float4 b){
  return make_float4(fmaxf(a.x,b.x), fmaxf(a.y,b.y), fmaxf(a.z,b.z), fmaxf(a.w,b.w));
}
template<bool MX> __device__ __forceinline__ float opf(float a, float b){
  return MX ? fmaxf(a,b) : fminf(a,b);
}
template<bool MX> __device__ __forceinline__ float4 opf4(float4 a, float4 b){
  return MX ? f4max(a,b) : f4min(a,b);
}

// 3-wide sliding window over 4 consecutive w-outputs
template<bool MX>
__device__ __forceinline__ float4 rw3(const float* rp, int w0){
  const float pad = MX ? -1e30f : 1e30f;
  float  l  = (w0 > 0)      ? rp[-1] : pad;
  float4 v  = ld4(rp);
  float  rr = (w0 + 4 < WW) ? rp[4]  : pad;
  float4 o;
  o.x = opf<MX>(opf<MX>(l,  v.x), v.y);
  o.y = opf<MX>(opf<MX>(v.x,v.y), v.z);
  o.z = opf<MX>(opf<MX>(v.y,v.z), v.w);
  o.w = opf<MX>(opf<MX>(v.z,v.w), rr);
  return o;
}

// 3x3x3 box pool over a 4x4 tile (rows h0..h0+3), SAME padding.
template<bool MX>
__device__ __forceinline__ void box27_4(const float* cp, int d, int h0, int w0, float4 out[4]){
  const float pad = MX ? -1e30f : 1e30f;
  const float4 P4 = make_float4(pad,pad,pad,pad);
  out[0]=out[1]=out[2]=out[3]=P4;
  #pragma unroll
  for (int dz=-1; dz<=1; ++dz){
    if ((unsigned)(d+dz) >= DD) continue;
    const float* sp = cp + dz*HWS;
    float4 rw[6];
    rw[0] = (h0 > 0)      ? rw3<MX>(sp - WW, w0)   : P4;
    #pragma unroll
    for (int j=0;j<4;j++) rw[j+1] = rw3<MX>(sp + j*WW, w0);
    rw[5] = (h0 + 4 < HH) ? rw3<MX>(sp + 4*WW, w0) : P4;
    #pragma unroll
    for (int j=0;j<4;j++)
      out[j] = opf4<MX>(out[j], opf4<MX>(rw[j], opf4<MX>(rw[j+1], rw[j+2])));
  }
}

// coordinates for 4x4-tile kernels
__device__ __forceinline__ void tcoords(int tt, int& w0, int& h0, int& d, int& vb){
  w0 = (tt & 31) << 2;
  h0 = ((tt >> 5) & 31) << 2;
  d  = (tt >> 10) & 63;
  vb = tt >> 16;               // field-item index (one per VOLSZ)
}

// ---------------- reductions ----------------
__device__ __forceinline__ float warp_sum(float v){
  #pragma unroll
  for (int o=16; o; o>>=1) v += __shfl_down_sync(0xffffffffu, v, o);
  return v;
}
__device__ __forceinline__ void block_add(double* dst, float v){
  __shared__ float sh[8];
  v = warp_sum(v);
  if ((threadIdx.x & 31) == 0) sh[threadIdx.x >> 5] = v;
  __syncthreads();
  if (threadIdx.x == 0){
    float t = sh[0]+sh[1]+sh[2]+sh[3]+sh[4]+sh[5]+sh[6]+sh[7];
    atomicAdd(dst, (double)t);
  }
  __syncthreads();
}
__device__ __forceinline__ void block_maxf(int* dst, float v){
  __shared__ float sh[8];
  #pragma unroll
  for (int o=16; o; o>>=1) v = fmaxf(v, __shfl_down_sync(0xffffffffu, v, o));
  if ((threadIdx.x & 31) == 0) sh[threadIdx.x >> 5] = v;
  __syncthreads();
  if (threadIdx.x == 0){
    float m = sh[0];
    #pragma unroll
    for (int k=1;k<8;k++) m = fmaxf(m, sh[k]);
    atomicMax(dst, __float_as_int(m));
  }
  __syncthreads();
}
__device__ __forceinline__ void block_minf(int* dst, float v){
  __shared__ float sh[8];
  #pragma unroll
  for (int o=16; o; o>>=1) v = fminf(v, __shfl_down_sync(0xffffffffu, v, o));
  if ((threadIdx.x & 31) == 0) sh[threadIdx.x >> 5] = v;
  __syncthreads();
  if (threadIdx.x == 0){
    float m = sh[0];
    #pragma unroll
    for (int k=1;k<8;k++) m = fminf(m, sh[k]);
    atomicMin(dst, __float_as_int(m));
  }
  __syncthreads();
}

// ---------------- kernels ----------------
__global__ void zero_kernel(){
  int t = threadIdx.x;
  if (t < 14) g_sums[t] = 0.0;
  if (t < 2){
    g_maxT[t] = 0; g_maxP[t] = 0;
    g_minT[t] = 0x7f800000; g_minP[t] = 0x7f800000;
  }
}

// prob/y/hard into stacked SRC + dice/CE/conn sums
__global__ void __launch_bounds__(256) init_kernel(const float* __restrict__ net,
                                                   const int* __restrict__ tgt){
  int t = blockIdx.x*256 + threadIdx.x;
  int i = t << 2;
  int b = i >> 20;
  float4 n0 = ld4(net + i + b*VOLSZ);
  float4 n1 = ld4(net + i + (b+1)*VOLSZ);
  int4   tg = *reinterpret_cast<const int4*>(tgt + i);
  float a[4] = {n0.x, n0.y, n0.z, n0.w};
  float c[4] = {n1.x, n1.y, n1.z, n1.w};
  int   l[4] = {tg.x, tg.y, tg.z, tg.w};
  float pv[4], yv[4], hv[4];
  float tp=0.f, fp=0.f, fn=0.f, ce=0.f, cn=0.f;
  #pragma unroll
  for (int k=0;k<4;k++){
    float y = (l[k] > 0) ? 1.f : 0.f;
    float p = 1.f / (1.f + expf(a[k] - c[k]));
    pv[k]=p; yv[k]=y; hv[k] = (p > 0.5f) ? 1.f : 0.f;
    tp += p*y; fp += p*(1.f-y); fn += (1.f-p)*y;
    float m = fmaxf(a[k], c[k]);
    float lse = m + logf(expf(a[k]-m) + expf(c[k]-m));
    ce += lse - ((l[k] > 0) ? c[k] : a[k]);
    cn += fabsf(((a[k] > 0.5f) ? 1.f : 0.f) - y)
        + fabsf(((c[k] > 0.5f) ? 1.f : 0.f) - y);
  }
  st4(g_SRC + i,          make_float4(yv[0],yv[1],yv[2],yv[3]));  // Y
  st4(g_SRC + NTOT + i,   make_float4(pv[0],pv[1],pv[2],pv[3]));  // P
  st4(g_SRC + 2*NTOT + i, make_float4(hv[0],hv[1],hv[2],hv[3]));  // Hd
  block_add(&g_sums[S_TP], tp);
  block_add(&g_sums[S_FP], fp);
  block_add(&g_sums[S_FN], fn);
  block_add(&g_sums[S_CE], ce);
  block_add(&g_sums[S_CONN], cn);
}

// directional (Sobel) loss — replicates the reference's exact kernel layout
__global__ void __launch_bounds__(256) dir_kernel(const float* __restrict__ net,
                                                  const int* __restrict__ tgt){
  int t = blockIdx.x*256 + threadIdx.x;
  int i = t << 2;
  int b = i >> 20;
  int r = i & (VOLSZ-1);
  int d = r >> 14, hh = (r >> 7) & 127, w0 = r & 127;
  const float* pb = net + i + b*VOLSZ;   // channel 0
  const int*   tb = tgt + i;
  float pgx[4]={0,0,0,0}, pgy[4]={0,0,0,0}, pgz[4]={0,0,0,0};
  float tgx[4]={0,0,0,0}, tgy[4]={0,0,0,0}, tgz[4]={0,0,0,0};
  #pragma unroll
  for (int dz=-1; dz<=1; ++dz){
    if ((unsigned)(d+dz) >= DD) continue;
    float cy = (dz==0) ? 2.f : 1.f;
    float cz = (float)dz;
    #pragma unroll
    for (int dy=-1; dy<=1; ++dy){
      if ((unsigned)(hh+dy) >= HH) continue;
      float cx = (dy==0) ? 2.f : 1.f;
      int off = dz*HWS + dy*WW;
      {
        const float* rp = pb + off;
        float vv[6];
        vv[0] = (w0 > 0) ? rp[-1] : 0.f;
        float4 v = ld4(rp);
        vv[1]=v.x; vv[2]=v.y; vv[3]=v.z; vv[4]=v.w;
        vv[5] = (w0 + 4 < WW) ? rp[4] : 0.f;
        #pragma unroll
        for (int k=0;k<4;k++){
          float dv = vv[k+2] - vv[k];
          float sv = vv[k] + 2.f*vv[k+1] + vv[k+2];
          pgx[k] += cx*dv; pgy[k] += cy*dv; pgz[k] += cz*sv;
        }
      }
      {
        const int* rp = tb + off;
        float vv[6];
        vv[0] = (w0 > 0) ? (float)rp[-1] : 0.f;
        int4 v = *reinterpret_cast<const int4*>(rp);
        vv[1]=(float)v.x; vv[2]=(float)v.y; vv[3]=(float)v.z; vv[4]=(float)v.w;
        vv[5] = (w0 + 4 < WW) ? (float)rp[4] : 0.f;
        #pragma unroll
        for (int k=0;k<4;k++){
          float dv = vv[k+2] - vv[k];
          float sv = vv[k] + 2.f*vv[k+1] + vv[k+2];
          tgx[k] += cx*dv; tgy[k] += cy*dv; tgz[k] += cz*sv;
        }
      }
    }
  }
  float acc = 0.f;
  #pragma unroll
  for (int k=0;k<4;k++){
    float np = sqrtf(pgx[k]*pgx[k] + pgy[k]*pgy[k] + pgz[k]*pgz[k]);
    float nt = sqrtf(tgx[k]*tgx[k] + tgy[k]*tgy[k] + tgz[k]*tgz[k]);
    float ip = 1.f / fmaxf(np, 1e-12f);
    float it = 1.f / fmaxf(nt, 1e-12f);
    float num = (pgx[k]*tgx[k] + pgy[k]*tgy[k] + pgz[k]*tgz[k]) * ip * it;
    float den = fmaxf((np*ip) * (nt*it), 1e-8f);
    acc += num / den;
  }
  block_add(&g_sums[S_DIR], acc);
}

// soft_erode (7-pt cross min), 4x4 tile, batched fields
__global__ void __launch_bounds__(256) erode4_kernel(const float* __restrict__ src,
                                                     float* __restrict__ dst){
  int tt = blockIdx.x*256 + threadIdx.x;
  int w0,h0,d,vb; tcoords(tt,w0,h0,d,vb);
  int off = vb*VOLSZ + d*HWS + h0*WW + w0;
  const float* p = src + off;
  float* q = dst + off;
  const float4 INF4 = make_float4(1e30f,1e30f,1e30f,1e30f);
  float4 plain[6];
  plain[0] = (h0 > 0) ? ld4(p - WW) : INF4;
  #pragma unroll
  for (int j=0;j<4;j++) plain[j+1] = ld4(p + j*WW);
  plain[5] = (h0 + 4 < HH) ? ld4(p + 4*WW) : INF4;
  #pragma unroll
  for (int j=0;j<4;j++){
    float4 v = plain[j+1];
    float l = (w0 > 0)      ? p[j*WW - 1] : 1e30f;
    float r = (w0 + 4 < WW) ? p[j*WW + 4] : 1e30f;
    float4 w3;
    w3.x = fminf(fminf(l,  v.x), v.y);
    w3.y = fminf(fminf(v.x,v.y), v.z);
    w3.z = fminf(fminf(v.y,v.z), v.w);
    w3.w = fminf(fminf(v.z,v.w), r);
    float4 mm = f4min(w3, f4min(plain[j], plain[j+2]));
    if (d > 0)    mm = f4min(mm, ld4(p - HWS + j*WW));
    if (d < DD-1) mm = f4min(mm, ld4(p + HWS + j*WW));
    st4(q + j*WW, mm);
  }
}

// skel = relu(img - dilate27(er)), 4x4 tile
__global__ void __launch_bounds__(256) dilate_init4_kernel(const float* __restrict__ img,
                                                           const float* __restrict__ er,
                                                           float* __restrict__ skel){
  int tt = blockIdx.x*256 + threadIdx.x;
  int w0,h0,d,vb; tcoords(tt,w0,h0,d,vb);
  int off = vb*VOLSZ + d*HWS + h0*WW + w0;
  float4 o[4];
  box27_4<true>(er + off, d, h0, w0, o);
  #pragma unroll
  for (int j=0;j<4;j++){
    float4 im = ld4(img + off + j*WW);
    st4(skel + off + j*WW,
        make_float4(fmaxf(im.x-o[j].x,0.f), fmaxf(im.y-o[j].y,0.f),
                    fmaxf(im.z-o[j].z,0.f), fmaxf(im.w-o[j].w,0.f)));
  }
}

// delta = relu(img - dilate27(er)); skel += relu(delta - skel*delta), 4x4 tile
__global__ void __launch_bounds__(256) dilate_update4_kernel(const float* __restrict__ img,
                                                             const float* __restrict__ er,
                                                             float* __restrict__ skel){
  int tt = blockIdx.x*256 + threadIdx.x;
  int w0,h0,d,vb; tcoords(tt,w0,h0,d,vb);
  int off = vb*VOLSZ + d*HWS + h0*WW + w0;
  float4 o[4];
  box27_4<true>(er + off, d, h0, w0, o);
  #pragma unroll
  for (int j=0;j<4;j++){
    float4 im = ld4(img + off + j*WW);
    float4 s  = ld4(skel + off + j*WW);
    float dl;
    dl = fmaxf(im.x-o[j].x,0.f); s.x += fmaxf(dl - s.x*dl, 0.f);
    dl = fmaxf(im.y-o[j].y,0.f); s.y += fmaxf(dl - s.y*dl, 0.f);
    dl = fmaxf(im.z-o[j].z,0.f); s.z += fmaxf(dl - s.z*dl, 0.f);
    dl = fmaxf(im.w-o[j].w,0.f); s.w += fmaxf(dl - s.w*dl, 0.f);
    st4(skel + off + j*WW, s);
  }
}

// edt step: acc += cur ; nxt = minpool27(cur), 4x4 tile, 2 fields batched.
// first=1: cur points to g_SRC; map vb -> {Y,Hd} field offsets.
__global__ void __launch_bounds__(256) minpool_acc4_kernel(const float* __restrict__ cur,
                                                           float* __restrict__ nxt,
                                                           float* __restrict__ acc,
                                                           int first){
  int tt = blockIdx.x*256 + threadIdx.x;
  int w0,h0,d,vb; tcoords(tt,w0,h0,d,vb);
  int off = d*HWS + h0*WW + w0;
  int sb  = first ? ((vb & 2)*NTOT + (vb & 1)*VOLSZ) : vb*VOLSZ;  // vb>>1 in {0:Y,1:Hd}
  int ob  = vb*VOLSZ + off;
  const float* p = cur + sb + off;
  float4 o[4];
  box27_4<false>(p, d, h0, w0, o);
  #pragma unroll
  for (int j=0;j<4;j++) st4(nxt + ob + j*WW, o[j]);
  if (first){
    #pragma unroll
    for (int j=0;j<4;j++) st4(acc + ob + j*WW, ld4(p + j*WW));
  } else {
    #pragma unroll
    for (int j=0;j<4;j++){
      float4 a = ld4(acc + ob + j*WW);
      float4 c = ld4(p + j*WW);
      a.x += c.x; a.y += c.y; a.z += c.z; a.w += c.w;
      st4(acc + ob + j*WW, a);
    }
  }
}

// per-batch max/min of skel_radius for both get_weights calls
__global__ void __launch_bounds__(256) r1_kernel(){
  int i = blockIdx.x*256 + threadIdx.x;
  int b = i >> 20;
  float y   = g_SRC[i];
  float p   = g_SRC[NTOT + i];
  float hd  = g_SRC[2*NTOT + i];
  float st  = g_SK[i];
  float sph = g_SK[2*NTOT + i];
  float srT = g_ACC[i] * y * st;
  float sb  = (sph * p > 0.5f) ? 1.f : 0.f;
  float srP = g_ACC[NTOT + i] * hd * sb;
  block_maxf(&g_maxT[b], srT);
  block_minf(&g_minT[b], srT);
  block_maxf(&g_maxP[b], srP);
  block_minf(&g_minP[b], srP);
}

// all union-loss + clDice sums in one pass
__global__ void __launch_bounds__(256) r2_kernel(){
  int i = blockIdx.x*256 + threadIdx.x;
  int b = i >> 20;
  float y   = g_SRC[i];
  float p   = g_SRC[NTOT + i];
  float hd  = g_SRC[2*NTOT + i];
  float st  = g_SK[i];
  float sp  = g_SK[NTOT + i];
  float sph = g_SK[2*NTOT + i];
  float rmaxT = fmaxf(__int_as_float(g_maxT[b]), 1.f);
  float rminT = fmaxf(__int_as_float(g_minT[b]), 1.f);
  float rmaxP = fmaxf(__int_as_float(g_maxP[b]), 1.f);
  float rminP = fmaxf(__int_as_float(g_minP[b]), 1.f);

  float dT  = g_ACC[i] * y;
  float srT = dT * st;
  float q_vl = fminf(dT, rmaxT) / rmaxT * y;
  float t1 = (rmaxT - srT + rminT) / rmaxT;
  float q_sl = t1*t1 * st * st;

  float dP  = g_ACC[NTOT + i] * hd;
  float sb  = (sph * p > 0.5f) ? 1.f : 0.f;
  float srP = dP * sb;
  float q_vp = fminf(dP, rmaxP) / rmaxP * p;
  float t2 = (rmaxP - srP + rminP) / rmaxP;
  float q_sp = t2*t2 * sb * (sph * p);

  float i1 = q_sp * powf(q_sp + 1e-4f, 0.7f) * q_vl;
  float u1 = q_sp * (0.1f*q_sp + 0.9f*q_vl);
  float i2 = q_sl * powf(q_vp + 1e-4f, 0.7f) * q_sl;
  float u2 = q_sl * (0.1f*q_vp + 0.9f*q_sl);

  block_add(&g_sums[S_I1], i1);
  block_add(&g_sums[S_U1], u1);
  block_add(&g_sums[S_I2], i2);
  block_add(&g_sums[S_U2], u2);
  block_add(&g_sums[S_CL1], sp*y);
  block_add(&g_sums[S_CL2], sp);
  block_add(&g_sums[S_CL3], st*p);
  block_add(&g_sums[S_CL4], st);
}

__global__ void final_kernel(float* __restrict__ out){
  double tp = g_sums[S_TP], fp = g_sums[S_FP], fn = g_sums[S_FN];
  double dice = -((2.0*tp + 1e-5) / (2.0*tp + fp + fn + 1e-5));
  double ce   = g_sums[S_CE] / (double)NTOT;
  double conn = g_sums[S_CONN] / (2.0 * (double)NTOT);
  double dir  = 1.0 - g_sums[S_DIR] / (double)NTOT;
  double tprec = (g_sums[S_CL1] + 1.0) / (g_sums[S_CL2] + 1.0);
  double tsens = (g_sums[S_CL3] + 1.0) / (g_sums[S_CL4] + 1.0);
  double cl = 1.0 - 2.0*tprec*tsens / (tprec + tsens);
  double u  = (1.0 - (g_sums[S_I1] + 1.0) / (g_sums[S_U1] + 1.0))
            + (1.0 - (g_sums[S_I2] + 1.0) / (g_sums[S_U2] + 1.0));
  out[0] = (float)(dice + ce + cl + dir + conn + u);
}

// ---------------- host orchestration ----------------
extern "C" void kernel_launch(void* const* d_in, const int* in_sizes, int n_in,
                              void* d_out, int out_size){
  (void)in_sizes; (void)n_in; (void)out_size;
  const float* net = (const float*)d_in[0];
  const int*   tgt = (const int*)d_in[1];
  float* out = (float*)d_out;

  float *SRC,*SK,*A,*Bb,*E,*ACC;
  cudaGetSymbolAddress((void**)&SRC, g_SRC);
  cudaGetSymbolAddress((void**)&SK,  g_SK);
  cudaGetSymbolAddress((void**)&A,   g_A);
  cudaGetSymbolAddress((void**)&Bb,  g_Bb);
  cudaGetSymbolAddress((void**)&E,   g_E);
  cudaGetSymbolAddress((void**)&ACC, g_ACC);

  zero_kernel<<<1,32>>>();
  init_kernel<<<G_INIT,256>>>(net, tgt);
  dir_kernel<<<G_INIT,256>>>(net, tgt);

  // --- batched soft_skel over 3 fields (Y, P, Hd) ---
  erode4_kernel<<<G_SKEL,256>>>(SRC, E);
  dilate_init4_kernel<<<G_SKEL,256>>>(SRC, E, SK);
  const float* cur = SRC;
  for (int it=0; it<10; ++it){
    float* nxt = (it & 1) ? Bb : A;
    erode4_kernel<<<G_SKEL,256>>>(cur, nxt);
    erode4_kernel<<<G_SKEL,256>>>(nxt, E);
    dilate_update4_kernel<<<G_SKEL,256>>>(nxt, E, SK);
    cur = nxt;
  }

  // --- batched edt_approx over 2 fields (Y, Hd) ---
  const float* ec = SRC;
  for (int k=0; k<16; ++k){
    float* nxt = (k & 1) ? Bb : A;     // reuse ping-pong (first 2*NTOT region)
    minpool_acc4_kernel<<<G_EDT,256>>>(ec, nxt, ACC, (k==0) ? 1 : 0);
    ec = nxt;
  }

  r1_kernel<<<GS,256>>>();
  r2_kernel<<<GS,256>>>();
  final_kernel<<<1,1>>>(out);
}